// round 3
// baseline (speedup 1.0000x reference)
#include <cuda_runtime.h>
#include <cuda_bf16.h>
#include <cstdint>

#define N_NODES 50000
#define N_EDGES 800000
#define IN_DIM  256
#define OUT_DIM 64

// ---- device-global scratch (allocation-free rule) ----
__device__ float g_support[(size_t)N_NODES * OUT_DIM];   // 12.8 MB
__device__ int   g_count[N_NODES];                       // per-dst degree
__device__ int   g_off[N_NODES + 1];                     // CSR offsets (exclusive)
__device__ int   g_cursor[N_NODES];                      // build cursors
__device__ int2  g_edges[N_EDGES];                       // (src, val-bits) sorted by dst

// ---------------------------------------------------------------------------
// Kernel: support = X @ W   (M=50000, K=256, N=64)
// 64x64 block tile, 256 threads, 4x4 micro-tile, packed f32x2 FMAs.
// ---------------------------------------------------------------------------
__global__ __launch_bounds__(256) void gemm_kernel(const float* __restrict__ X,
                                                   const float* __restrict__ W) {
    __shared__ float sAT[64][68];
    __shared__ float sW[64][64];

    const int tid = threadIdx.x;
    const int tx  = tid & 15;
    const int ty  = tid >> 4;
    const int row0 = blockIdx.x * 64;

    unsigned long long acc[4][2];
#pragma unroll
    for (int i = 0; i < 4; i++) { acc[i][0] = 0ULL; acc[i][1] = 0ULL; }

    for (int kc = 0; kc < IN_DIM; kc += 64) {
        {
            const int r  = tid & 63;
            const int kg = tid >> 6;
            const int grow = row0 + r;
#pragma unroll
            for (int j = 0; j < 4; j++) {
                const int k4 = kg + j * 4;
                float4 v = make_float4(0.f, 0.f, 0.f, 0.f);
                if (grow < N_NODES)
                    v = *reinterpret_cast<const float4*>(
                        X + (size_t)grow * IN_DIM + kc + k4 * 4);
                sAT[k4 * 4 + 0][r] = v.x;
                sAT[k4 * 4 + 1][r] = v.y;
                sAT[k4 * 4 + 2][r] = v.z;
                sAT[k4 * 4 + 3][r] = v.w;
            }
        }
        {
            const int c4 = tid & 15;
            const int kk = tid >> 4;
#pragma unroll
            for (int j = 0; j < 4; j++) {
                const int k = kk + j * 16;
                float4 v = *reinterpret_cast<const float4*>(
                    W + (size_t)(kc + k) * OUT_DIM + c4 * 4);
                *reinterpret_cast<float4*>(&sW[k][c4 * 4]) = v;
            }
        }
        __syncthreads();

#pragma unroll
        for (int kk = 0; kk < 64; kk++) {
            float4 a = *reinterpret_cast<const float4*>(&sAT[kk][ty * 4]);
            float4 b = *reinterpret_cast<const float4*>(&sW[kk][tx * 4]);
            unsigned long long b01, b23;
            asm("mov.b64 %0, {%1,%2};" : "=l"(b01)
                : "r"(__float_as_uint(b.x)), "r"(__float_as_uint(b.y)));
            asm("mov.b64 %0, {%1,%2};" : "=l"(b23)
                : "r"(__float_as_uint(b.z)), "r"(__float_as_uint(b.w)));
            float ar[4] = {a.x, a.y, a.z, a.w};
#pragma unroll
            for (int i = 0; i < 4; i++) {
                unsigned long long aa;
                asm("mov.b64 %0, {%1,%1};" : "=l"(aa)
                    : "r"(__float_as_uint(ar[i])));
                asm("fma.rn.f32x2 %0, %1, %2, %0;"
                    : "+l"(acc[i][0]) : "l"(aa), "l"(b01));
                asm("fma.rn.f32x2 %0, %1, %2, %0;"
                    : "+l"(acc[i][1]) : "l"(aa), "l"(b23));
            }
        }
        __syncthreads();
    }

#pragma unroll
    for (int i = 0; i < 4; i++) {
        const int grow = row0 + ty * 4 + i;
        if (grow < N_NODES) {
            unsigned int x0, x1, x2, x3;
            asm("mov.b64 {%0,%1}, %2;" : "=r"(x0), "=r"(x1) : "l"(acc[i][0]));
            asm("mov.b64 {%0,%1}, %2;" : "=r"(x2), "=r"(x3) : "l"(acc[i][1]));
            float4 o = make_float4(__uint_as_float(x0), __uint_as_float(x1),
                                   __uint_as_float(x2), __uint_as_float(x3));
            *reinterpret_cast<float4*>(g_support + (size_t)grow * OUT_DIM + tx * 4) = o;
        }
    }
}

// ---------------------------------------------------------------------------
// CSR build: zero counts -> histogram -> scan -> scatter edges
// ---------------------------------------------------------------------------
__global__ __launch_bounds__(256) void zero_kernel() {
    int i = blockIdx.x * blockDim.x + threadIdx.x;
    if (i < N_NODES) g_count[i] = 0;
}

__global__ __launch_bounds__(256) void hist_kernel(const int* __restrict__ edge_dst) {
    int i = blockIdx.x * blockDim.x + threadIdx.x;
    if (i < N_EDGES) atomicAdd(&g_count[edge_dst[i]], 1);
}

// Single-block, 1024-thread two-pass exclusive scan over 50K counts.
__global__ __launch_bounds__(1024) void scan_kernel() {
    __shared__ int warpsum[32];
    const int T = 1024;
    const int t = threadIdx.x;
    const int CH = (N_NODES + T - 1) / T;           // 49
    const int base = t * CH;
    const int lim  = min(base + CH, N_NODES);

    int sum = 0;
    for (int i = base; i < lim; i++) sum += g_count[i];

    // block-wide exclusive scan of per-thread sums
    const unsigned mask = 0xffffffffu;
    const int lane = t & 31, w = t >> 5;
    int v = sum;
#pragma unroll
    for (int d = 1; d < 32; d <<= 1) {
        int n = __shfl_up_sync(mask, v, d);
        if (lane >= d) v += n;
    }
    if (lane == 31) warpsum[w] = v;
    __syncthreads();
    if (w == 0) {
        int x = warpsum[lane];
#pragma unroll
        for (int d = 1; d < 32; d <<= 1) {
            int n = __shfl_up_sync(mask, x, d);
            if (lane >= d) x += n;
        }
        warpsum[lane] = x;
    }
    __syncthreads();
    int excl = v - sum + (w > 0 ? warpsum[w - 1] : 0);

    int run = excl;
    for (int i = base; i < lim; i++) {
        g_off[i] = run;
        g_cursor[i] = run;
        run += g_count[i];
    }
    if (t == T - 1) g_off[N_NODES] = N_EDGES;
}

__global__ __launch_bounds__(256) void build_kernel(const float* __restrict__ edge_val,
                                                    const int* __restrict__ edge_src,
                                                    const int* __restrict__ edge_dst) {
    int i = blockIdx.x * blockDim.x + threadIdx.x;
    if (i < N_EDGES) {
        int d = edge_dst[i];
        int pos = atomicAdd(&g_cursor[d], 1);
        g_edges[pos] = make_int2(edge_src[i], __float_as_int(edge_val[i]));
    }
}

// ---------------------------------------------------------------------------
// Segmented SpMM: one warp per dst node, 2 output cols per lane,
// register accumulation, bias folded in, single float2 store. No atomics.
// ---------------------------------------------------------------------------
__global__ __launch_bounds__(256) void spmm_kernel(const float* __restrict__ bias,
                                                   float* __restrict__ out) {
    const int gw   = (blockIdx.x * 256 + threadIdx.x) >> 5;   // global warp id = node
    const int lane = threadIdx.x & 31;
    if (gw >= N_NODES) return;

    const int beg = g_off[gw];
    const int end = g_off[gw + 1];

    float2 acc = reinterpret_cast<const float2*>(bias)[lane];
    const float2* sup = reinterpret_cast<const float2*>(g_support);

    int e = beg;
    for (; e + 1 < end; e += 2) {
        int2 p0 = g_edges[e];
        int2 p1 = g_edges[e + 1];
        float2 s0 = sup[(size_t)p0.x * 32 + lane];
        float2 s1 = sup[(size_t)p1.x * 32 + lane];
        float v0 = __int_as_float(p0.y);
        float v1 = __int_as_float(p1.y);
        acc.x = fmaf(v0, s0.x, acc.x);
        acc.y = fmaf(v0, s0.y, acc.y);
        acc.x = fmaf(v1, s1.x, acc.x);
        acc.y = fmaf(v1, s1.y, acc.y);
    }
    if (e < end) {
        int2 p = g_edges[e];
        float2 s = sup[(size_t)p.x * 32 + lane];
        float v = __int_as_float(p.y);
        acc.x = fmaf(v, s.x, acc.x);
        acc.y = fmaf(v, s.y, acc.y);
    }

    reinterpret_cast<float2*>(out)[(size_t)gw * 32 + lane] = acc;
}

// ---------------------------------------------------------------------------
extern "C" void kernel_launch(void* const* d_in, const int* in_sizes, int n_in,
                              void* d_out, int out_size) {
    const float* X    = (const float*)d_in[0];     // [50000, 256]
    const float* W    = (const float*)d_in[1];     // [256, 64]
    const float* bias = (const float*)d_in[2];     // [64]
    const float* ev   = (const float*)d_in[3];     // [800000]
    const int*   es   = (const int*)d_in[4];       // [800000] int32
    const int*   ed   = (const int*)d_in[5];       // [800000] int32
    float* out = (float*)d_out;                    // [50000, 64]

    gemm_kernel<<<(N_NODES + 63) / 64, 256>>>(X, W);

    zero_kernel<<<(N_NODES + 255) / 256, 256>>>();
    hist_kernel<<<(N_EDGES + 255) / 256, 256>>>(ed);
    scan_kernel<<<1, 1024>>>();
    build_kernel<<<(N_EDGES + 255) / 256, 256>>>(ev, es, ed);

    const int warps_total = N_NODES;
    spmm_kernel<<<(warps_total * 32 + 255) / 256, 256>>>(bias, out);
}

// round 4
// speedup vs baseline: 1.6448x; 1.6448x over previous
#include <cuda_runtime.h>
#include <cuda_bf16.h>
#include <cstdint>

#define N_NODES 50000
#define N_EDGES 800000
#define IN_DIM  256
#define OUT_DIM 64
#define SCAN_BS 256
#define SCAN_NB ((N_NODES + SCAN_BS - 1) / SCAN_BS)   // 196

// ---- device-global scratch (allocation-free rule) ----
__device__ float g_support[(size_t)N_NODES * OUT_DIM];   // 12.8 MB
__device__ int   g_count[N_NODES];                       // per-dst degree
__device__ int   g_off[N_NODES + 1];                     // CSR offsets (exclusive)
__device__ int   g_cursor[N_NODES];                      // build cursors
__device__ int   g_blocksum[SCAN_NB];                    // scan partials
__device__ int   g_blockpre[SCAN_NB];                    // scanned partials
__device__ int2  g_edges[N_EDGES];                       // (src, val-bits) sorted by dst

// ---------------------------------------------------------------------------
// Kernel: support = X @ W   (M=50000, K=256, N=64)
// 64x64 block tile, 256 threads, 4x4 micro-tile, packed f32x2 FMAs.
// ---------------------------------------------------------------------------
__global__ __launch_bounds__(256) void gemm_kernel(const float* __restrict__ X,
                                                   const float* __restrict__ W) {
    __shared__ float sAT[64][68];
    __shared__ float sW[64][64];

    const int tid = threadIdx.x;
    const int tx  = tid & 15;
    const int ty  = tid >> 4;
    const int row0 = blockIdx.x * 64;

    unsigned long long acc[4][2];
#pragma unroll
    for (int i = 0; i < 4; i++) { acc[i][0] = 0ULL; acc[i][1] = 0ULL; }

    for (int kc = 0; kc < IN_DIM; kc += 64) {
        {
            const int r  = tid & 63;
            const int kg = tid >> 6;
            const int grow = row0 + r;
#pragma unroll
            for (int j = 0; j < 4; j++) {
                const int k4 = kg + j * 4;
                float4 v = make_float4(0.f, 0.f, 0.f, 0.f);
                if (grow < N_NODES)
                    v = *reinterpret_cast<const float4*>(
                        X + (size_t)grow * IN_DIM + kc + k4 * 4);
                sAT[k4 * 4 + 0][r] = v.x;
                sAT[k4 * 4 + 1][r] = v.y;
                sAT[k4 * 4 + 2][r] = v.z;
                sAT[k4 * 4 + 3][r] = v.w;
            }
        }
        {
            const int c4 = tid & 15;
            const int kk = tid >> 4;
#pragma unroll
            for (int j = 0; j < 4; j++) {
                const int k = kk + j * 16;
                float4 v = *reinterpret_cast<const float4*>(
                    W + (size_t)(kc + k) * OUT_DIM + c4 * 4);
                *reinterpret_cast<float4*>(&sW[k][c4 * 4]) = v;
            }
        }
        __syncthreads();

#pragma unroll
        for (int kk = 0; kk < 64; kk++) {
            float4 a = *reinterpret_cast<const float4*>(&sAT[kk][ty * 4]);
            float4 b = *reinterpret_cast<const float4*>(&sW[kk][tx * 4]);
            unsigned long long b01, b23;
            asm("mov.b64 %0, {%1,%2};" : "=l"(b01)
                : "r"(__float_as_uint(b.x)), "r"(__float_as_uint(b.y)));
            asm("mov.b64 %0, {%1,%2};" : "=l"(b23)
                : "r"(__float_as_uint(b.z)), "r"(__float_as_uint(b.w)));
            float ar[4] = {a.x, a.y, a.z, a.w};
#pragma unroll
            for (int i = 0; i < 4; i++) {
                unsigned long long aa;
                asm("mov.b64 %0, {%1,%1};" : "=l"(aa)
                    : "r"(__float_as_uint(ar[i])));
                asm("fma.rn.f32x2 %0, %1, %2, %0;"
                    : "+l"(acc[i][0]) : "l"(aa), "l"(b01));
                asm("fma.rn.f32x2 %0, %1, %2, %0;"
                    : "+l"(acc[i][1]) : "l"(aa), "l"(b23));
            }
        }
        __syncthreads();
    }

#pragma unroll
    for (int i = 0; i < 4; i++) {
        const int grow = row0 + ty * 4 + i;
        if (grow < N_NODES) {
            unsigned int x0, x1, x2, x3;
            asm("mov.b64 {%0,%1}, %2;" : "=r"(x0), "=r"(x1) : "l"(acc[i][0]));
            asm("mov.b64 {%0,%1}, %2;" : "=r"(x2), "=r"(x3) : "l"(acc[i][1]));
            float4 o = make_float4(__uint_as_float(x0), __uint_as_float(x1),
                                   __uint_as_float(x2), __uint_as_float(x3));
            *reinterpret_cast<float4*>(g_support + (size_t)grow * OUT_DIM + tx * 4) = o;
        }
    }
}

// ---------------------------------------------------------------------------
// CSR build: zero -> histogram -> 3-phase hierarchical scan -> scatter edges
// ---------------------------------------------------------------------------
__global__ __launch_bounds__(256) void zero_kernel() {
    int i = blockIdx.x * blockDim.x + threadIdx.x;
    if (i < N_NODES) g_count[i] = 0;
}

__global__ __launch_bounds__(256) void hist_kernel(const int* __restrict__ edge_dst) {
    int i = blockIdx.x * blockDim.x + threadIdx.x;
    if (i < N_EDGES) atomicAdd(&g_count[edge_dst[i]], 1);
}

// Block-local inclusive scan of 256 ints via warp shuffles; returns inclusive
// value for this thread. warpsum must be __shared__ int[8].
__device__ __forceinline__ int block_scan_256(int v, int t, int* warpsum) {
    const unsigned m = 0xffffffffu;
    const int lane = t & 31, w = t >> 5;
#pragma unroll
    for (int d = 1; d < 32; d <<= 1) {
        int n = __shfl_up_sync(m, v, d);
        if (lane >= d) v += n;
    }
    if (lane == 31) warpsum[w] = v;
    __syncthreads();
    if (w == 0 && lane < 8) {
        int x = warpsum[lane];
#pragma unroll
        for (int d = 1; d < 8; d <<= 1) {
            int n = __shfl_up_sync(0xffu, x, d);
            if (lane >= d) x += n;
        }
        warpsum[lane] = x;
    }
    __syncthreads();
    return v + (w > 0 ? warpsum[w - 1] : 0);
}

// Phase 1: per-block exclusive scan + block sums.
__global__ __launch_bounds__(SCAN_BS) void scan_partial_kernel() {
    __shared__ int warpsum[8];
    const int t = threadIdx.x;
    const int i = blockIdx.x * SCAN_BS + t;
    const int v = (i < N_NODES) ? g_count[i] : 0;
    const int incl = block_scan_256(v, t, warpsum);
    if (i < N_NODES) g_off[i] = incl - v;                   // local exclusive
    if (t == SCAN_BS - 1) g_blocksum[blockIdx.x] = incl;    // block total
}

// Phase 2: exclusive scan of the 196 block sums (1 block).
__global__ __launch_bounds__(SCAN_BS) void scan_blocks_kernel() {
    __shared__ int warpsum[8];
    const int t = threadIdx.x;
    const int v = (t < SCAN_NB) ? g_blocksum[t] : 0;
    const int incl = block_scan_256(v, t, warpsum);
    if (t < SCAN_NB) g_blockpre[t] = incl - v;
}

// Phase 3: add block prefix; emit offsets + cursors (coalesced).
__global__ __launch_bounds__(SCAN_BS) void scan_add_kernel() {
    const int i = blockIdx.x * SCAN_BS + threadIdx.x;
    if (i < N_NODES) {
        const int o = g_off[i] + g_blockpre[blockIdx.x];
        g_off[i] = o;
        g_cursor[i] = o;
    }
    if (i == 0) g_off[N_NODES] = N_EDGES;
}

__global__ __launch_bounds__(256) void build_kernel(const float* __restrict__ edge_val,
                                                    const int* __restrict__ edge_src,
                                                    const int* __restrict__ edge_dst) {
    int i = blockIdx.x * blockDim.x + threadIdx.x;
    if (i < N_EDGES) {
        int d = edge_dst[i];
        int pos = atomicAdd(&g_cursor[d], 1);
        g_edges[pos] = make_int2(edge_src[i], __float_as_int(edge_val[i]));
    }
}

// ---------------------------------------------------------------------------
// Segmented SpMM: one warp per dst node, 2 output cols per lane,
// register accumulation, bias folded in, single float2 store. No atomics.
// ---------------------------------------------------------------------------
__global__ __launch_bounds__(256) void spmm_kernel(const float* __restrict__ bias,
                                                   float* __restrict__ out) {
    const int gw   = (blockIdx.x * 256 + threadIdx.x) >> 5;   // node id
    const int lane = threadIdx.x & 31;
    if (gw >= N_NODES) return;

    const int beg = g_off[gw];
    const int end = g_off[gw + 1];

    float2 acc = reinterpret_cast<const float2*>(bias)[lane];
    const float2* sup = reinterpret_cast<const float2*>(g_support);

    int e = beg;
    for (; e + 1 < end; e += 2) {
        int2 p0 = g_edges[e];
        int2 p1 = g_edges[e + 1];
        float2 s0 = sup[(size_t)p0.x * 32 + lane];
        float2 s1 = sup[(size_t)p1.x * 32 + lane];
        float v0 = __int_as_float(p0.y);
        float v1 = __int_as_float(p1.y);
        acc.x = fmaf(v0, s0.x, acc.x);
        acc.y = fmaf(v0, s0.y, acc.y);
        acc.x = fmaf(v1, s1.x, acc.x);
        acc.y = fmaf(v1, s1.y, acc.y);
    }
    if (e < end) {
        int2 p = g_edges[e];
        float2 s = sup[(size_t)p.x * 32 + lane];
        float v = __int_as_float(p.y);
        acc.x = fmaf(v, s.x, acc.x);
        acc.y = fmaf(v, s.y, acc.y);
    }

    reinterpret_cast<float2*>(out)[(size_t)gw * 32 + lane] = acc;
}

// ---------------------------------------------------------------------------
extern "C" void kernel_launch(void* const* d_in, const int* in_sizes, int n_in,
                              void* d_out, int out_size) {
    const float* X    = (const float*)d_in[0];     // [50000, 256]
    const float* W    = (const float*)d_in[1];     // [256, 64]
    const float* bias = (const float*)d_in[2];     // [64]
    const float* ev   = (const float*)d_in[3];     // [800000]
    const int*   es   = (const int*)d_in[4];       // [800000] int32
    const int*   ed   = (const int*)d_in[5];       // [800000] int32
    float* out = (float*)d_out;                    // [50000, 64]

    gemm_kernel<<<(N_NODES + 63) / 64, 256>>>(X, W);

    zero_kernel<<<(N_NODES + 255) / 256, 256>>>();
    hist_kernel<<<(N_EDGES + 255) / 256, 256>>>(ed);
    scan_partial_kernel<<<SCAN_NB, SCAN_BS>>>();
    scan_blocks_kernel<<<1, SCAN_BS>>>();
    scan_add_kernel<<<SCAN_NB, SCAN_BS>>>();
    build_kernel<<<(N_EDGES + 255) / 256, 256>>>(ev, es, ed);

    spmm_kernel<<<(N_NODES * 32 + 255) / 256, 256>>>(bias, out);
}

// round 6
// speedup vs baseline: 1.8865x; 1.1470x over previous
#include <cuda_runtime.h>
#include <cuda_bf16.h>
#include <cstdint>

#define N_NODES 50000
#define N_EDGES 800000
#define IN_DIM  256
#define OUT_DIM 64
#define SCAN_BS 256
#define SCAN_NB ((N_NODES + SCAN_BS - 1) / SCAN_BS)   // 196

// ---- device-global scratch (allocation-free rule) ----
__device__ float g_support[(size_t)N_NODES * OUT_DIM];   // 12.8 MB
__device__ float g_WT_hi[OUT_DIM * IN_DIM];              // W^T hi (tf32)
__device__ float g_WT_lo[OUT_DIM * IN_DIM];              // W^T lo (tf32)
__device__ int   g_count[N_NODES];
__device__ int   g_off[N_NODES + 1];
__device__ int   g_cursor[N_NODES];
__device__ int   g_blocksum[SCAN_NB];
__device__ int   g_blockpre[SCAN_NB];
__device__ int2  g_edges[N_EDGES];

__device__ __forceinline__ float to_tf32(float x) {
    uint32_t u;
    asm("cvt.rna.tf32.f32 %0, %1;" : "=r"(u) : "f"(x));
    return __uint_as_float(u);
}

// mma.sync m16n8k8 tf32 (sm_80+ plain feature — OK at .target sm_103)
__device__ __forceinline__ void mma_tf32(float* d, const float* a, float b0, float b1) {
    asm volatile(
        "mma.sync.aligned.m16n8k8.row.col.f32.tf32.tf32.f32 "
        "{%0,%1,%2,%3}, {%4,%5,%6,%7}, {%8,%9}, {%0,%1,%2,%3};"
        : "+f"(d[0]), "+f"(d[1]), "+f"(d[2]), "+f"(d[3])
        : "r"(__float_as_uint(a[0])), "r"(__float_as_uint(a[1])),
          "r"(__float_as_uint(a[2])), "r"(__float_as_uint(a[3])),
          "r"(__float_as_uint(b0)), "r"(__float_as_uint(b1)));
}

// ---------------------------------------------------------------------------
// Pre-kernel: W [K,N] -> W^T [N,K] split into tf32 hi/lo parts.
// ---------------------------------------------------------------------------
__global__ __launch_bounds__(256) void wt_kernel(const float* __restrict__ W) {
    int idx = blockIdx.x * 256 + threadIdx.x;           // 16384 total
    if (idx < OUT_DIM * IN_DIM) {
        int n = idx >> 8;            // 0..63
        int k = idx & 255;           // 0..255
        float x = W[k * OUT_DIM + n];
        float hi = to_tf32(x);
        g_WT_hi[idx] = hi;
        g_WT_lo[idx] = to_tf32(x - hi);
    }
}

// ---------------------------------------------------------------------------
// Tensor GEMM via mma.sync tf32 (3xTF32 hi/lo split for fp32-grade accuracy)
// support[M=50000, 64] = X[M, 256] @ W[256, 64]
// Block: 128-row tile, 8 warps (m16 stripe each), K chunked by 16.
// SMEM stride 20 words -> conflict-free fragment loads.
// ---------------------------------------------------------------------------
#define TILE_M 128
#define KC     16
#define NCHUNK (IN_DIM / KC)    // 16

__global__ __launch_bounds__(256) void gemm_mma_kernel(const float* __restrict__ X) {
    __shared__ float sAhi[TILE_M][20];
    __shared__ float sAlo[TILE_M][20];
    __shared__ float sBhi[OUT_DIM][20];
    __shared__ float sBlo[OUT_DIM][20];

    const int tid  = threadIdx.x;
    const int wid  = tid >> 5;
    const int lane = tid & 31;
    const int gid  = lane >> 2;     // 0..7
    const int tig  = lane & 3;      // 0..3
    const int row0 = blockIdx.x * TILE_M;

    float acc[8][4];
#pragma unroll
    for (int nt = 0; nt < 8; nt++)
#pragma unroll
        for (int q = 0; q < 4; q++) acc[nt][q] = 0.f;

    for (int ch = 0; ch < NCHUNK; ch++) {
        const int kc = ch * KC;
        // --- load + split A chunk: 128 rows x 16 k (2 float4 per thread) ---
#pragma unroll
        for (int i = tid; i < TILE_M * (KC / 4); i += 256) {
            const int r = i >> 2;       // row 0..127
            const int q = i & 3;        // float4 slot in 16 k
            const int grow = row0 + r;
            float4 x = make_float4(0.f, 0.f, 0.f, 0.f);
            if (grow < N_NODES)
                x = *reinterpret_cast<const float4*>(X + (size_t)grow * IN_DIM + kc + q * 4);
            float4 hi, lo;
            hi.x = to_tf32(x.x); lo.x = to_tf32(x.x - hi.x);
            hi.y = to_tf32(x.y); lo.y = to_tf32(x.y - hi.y);
            hi.z = to_tf32(x.z); lo.z = to_tf32(x.z - hi.z);
            hi.w = to_tf32(x.w); lo.w = to_tf32(x.w - hi.w);
            *reinterpret_cast<float4*>(&sAhi[r][q * 4]) = hi;
            *reinterpret_cast<float4*>(&sAlo[r][q * 4]) = lo;
        }
        // --- load B chunk (pre-split): 64 n x 16 k (1 float4 per thread) ---
        {
            const int n = tid >> 2;
            const int q = tid & 3;
            float4 hi = *reinterpret_cast<const float4*>(g_WT_hi + (size_t)n * IN_DIM + kc + q * 4);
            float4 lo = *reinterpret_cast<const float4*>(g_WT_lo + (size_t)n * IN_DIM + kc + q * 4);
            *reinterpret_cast<float4*>(&sBhi[n][q * 4]) = hi;
            *reinterpret_cast<float4*>(&sBlo[n][q * 4]) = lo;
        }
        __syncthreads();

#pragma unroll
        for (int ks = 0; ks < KC / 8; ks++) {
            const int k0 = ks * 8;
            float ahi[4], alo[4];
            const int ar = wid * 16 + gid;
            ahi[0] = sAhi[ar][k0 + tig];
            ahi[1] = sAhi[ar + 8][k0 + tig];
            ahi[2] = sAhi[ar][k0 + tig + 4];
            ahi[3] = sAhi[ar + 8][k0 + tig + 4];
            alo[0] = sAlo[ar][k0 + tig];
            alo[1] = sAlo[ar + 8][k0 + tig];
            alo[2] = sAlo[ar][k0 + tig + 4];
            alo[3] = sAlo[ar + 8][k0 + tig + 4];
#pragma unroll
            for (int nt = 0; nt < 8; nt++) {
                const int br = nt * 8 + gid;
                float bh0 = sBhi[br][k0 + tig];
                float bh1 = sBhi[br][k0 + tig + 4];
                float bl0 = sBlo[br][k0 + tig];
                float bl1 = sBlo[br][k0 + tig + 4];
                mma_tf32(acc[nt], ahi, bh0, bh1);   // hi*hi
                mma_tf32(acc[nt], alo, bh0, bh1);   // lo*hi
                mma_tf32(acc[nt], ahi, bl0, bl1);   // hi*lo
            }
        }
        __syncthreads();
    }

    // --- epilogue: write 16x64 per warp ---
    const int r0 = row0 + wid * 16 + gid;
#pragma unroll
    for (int nt = 0; nt < 8; nt++) {
        const int col = nt * 8 + tig * 2;
        if (r0 < N_NODES)
            *reinterpret_cast<float2*>(g_support + (size_t)r0 * OUT_DIM + col) =
                make_float2(acc[nt][0], acc[nt][1]);
        if (r0 + 8 < N_NODES)
            *reinterpret_cast<float2*>(g_support + (size_t)(r0 + 8) * OUT_DIM + col) =
                make_float2(acc[nt][2], acc[nt][3]);
    }
}

// ---------------------------------------------------------------------------
// CSR build: zero -> histogram -> 3-phase hierarchical scan -> scatter edges
// ---------------------------------------------------------------------------
__global__ __launch_bounds__(256) void zero_kernel() {
    int i = blockIdx.x * blockDim.x + threadIdx.x;
    if (i < N_NODES) g_count[i] = 0;
}

__global__ __launch_bounds__(256) void hist_kernel(const int* __restrict__ edge_dst) {
    int i = blockIdx.x * blockDim.x + threadIdx.x;
    if (i < N_EDGES) atomicAdd(&g_count[edge_dst[i]], 1);
}

__device__ __forceinline__ int block_scan_256(int v, int t, int* warpsum) {
    const unsigned m = 0xffffffffu;
    const int lane = t & 31, w = t >> 5;
#pragma unroll
    for (int d = 1; d < 32; d <<= 1) {
        int n = __shfl_up_sync(m, v, d);
        if (lane >= d) v += n;
    }
    if (lane == 31) warpsum[w] = v;
    __syncthreads();
    if (w == 0 && lane < 8) {
        int x = warpsum[lane];
#pragma unroll
        for (int d = 1; d < 8; d <<= 1) {
            int n = __shfl_up_sync(0xffu, x, d);
            if (lane >= d) x += n;
        }
        warpsum[lane] = x;
    }
    __syncthreads();
    return v + (w > 0 ? warpsum[w - 1] : 0);
}

__global__ __launch_bounds__(SCAN_BS) void scan_partial_kernel() {
    __shared__ int warpsum[8];
    const int t = threadIdx.x;
    const int i = blockIdx.x * SCAN_BS + t;
    const int v = (i < N_NODES) ? g_count[i] : 0;
    const int incl = block_scan_256(v, t, warpsum);
    if (i < N_NODES) g_off[i] = incl - v;
    if (t == SCAN_BS - 1) g_blocksum[blockIdx.x] = incl;
}

__global__ __launch_bounds__(SCAN_BS) void scan_blocks_kernel() {
    __shared__ int warpsum[8];
    const int t = threadIdx.x;
    const int v = (t < SCAN_NB) ? g_blocksum[t] : 0;
    const int incl = block_scan_256(v, t, warpsum);
    if (t < SCAN_NB) g_blockpre[t] = incl - v;
}

__global__ __launch_bounds__(SCAN_BS) void scan_add_kernel() {
    const int i = blockIdx.x * SCAN_BS + threadIdx.x;
    if (i < N_NODES) {
        const int o = g_off[i] + g_blockpre[blockIdx.x];
        g_off[i] = o;
        g_cursor[i] = o;
    }
    if (i == 0) g_off[N_NODES] = N_EDGES;
}

__global__ __launch_bounds__(256) void build_kernel(const float* __restrict__ edge_val,
                                                    const int* __restrict__ edge_src,
                                                    const int* __restrict__ edge_dst) {
    int i = blockIdx.x * blockDim.x + threadIdx.x;
    if (i < N_EDGES) {
        int d = edge_dst[i];
        int pos = atomicAdd(&g_cursor[d], 1);
        g_edges[pos] = make_int2(edge_src[i], __float_as_int(edge_val[i]));
    }
}

// ---------------------------------------------------------------------------
// Segmented SpMM: one warp per dst node, 2 cols/lane, bias folded, no atomics.
// ---------------------------------------------------------------------------
__global__ __launch_bounds__(256) void spmm_kernel(const float* __restrict__ bias,
                                                   float* __restrict__ out) {
    const int gw   = (blockIdx.x * 256 + threadIdx.x) >> 5;
    const int lane = threadIdx.x & 31;
    if (gw >= N_NODES) return;

    const int beg = g_off[gw];
    const int end = g_off[gw + 1];

    float2 acc = reinterpret_cast<const float2*>(bias)[lane];
    const float2* sup = reinterpret_cast<const float2*>(g_support);

    int e = beg;
    for (; e + 1 < end; e += 2) {
        int2 p0 = g_edges[e];
        int2 p1 = g_edges[e + 1];
        float2 s0 = sup[(size_t)p0.x * 32 + lane];
        float2 s1 = sup[(size_t)p1.x * 32 + lane];
        float v0 = __int_as_float(p0.y);
        float v1 = __int_as_float(p1.y);
        acc.x = fmaf(v0, s0.x, acc.x);
        acc.y = fmaf(v0, s0.y, acc.y);
        acc.x = fmaf(v1, s1.x, acc.x);
        acc.y = fmaf(v1, s1.y, acc.y);
    }
    if (e < end) {
        int2 p = g_edges[e];
        float2 s = sup[(size_t)p.x * 32 + lane];
        float v = __int_as_float(p.y);
        acc.x = fmaf(v, s.x, acc.x);
        acc.y = fmaf(v, s.y, acc.y);
    }

    reinterpret_cast<float2*>(out)[(size_t)gw * 32 + lane] = acc;
}

// ---------------------------------------------------------------------------
extern "C" void kernel_launch(void* const* d_in, const int* in_sizes, int n_in,
                              void* d_out, int out_size) {
    const float* X    = (const float*)d_in[0];     // [50000, 256]
    const float* W    = (const float*)d_in[1];     // [256, 64]
    const float* bias = (const float*)d_in[2];     // [64]
    const float* ev   = (const float*)d_in[3];     // [800000]
    const int*   es   = (const int*)d_in[4];       // [800000] int32
    const int*   ed   = (const int*)d_in[5];       // [800000] int32
    float* out = (float*)d_out;                    // [50000, 64]

    wt_kernel<<<(OUT_DIM * IN_DIM + 255) / 256, 256>>>(W);
    gemm_mma_kernel<<<(N_NODES + TILE_M - 1) / TILE_M, 256>>>(X);

    zero_kernel<<<(N_NODES + 255) / 256, 256>>>();
    hist_kernel<<<(N_EDGES + 255) / 256, 256>>>(ed);
    scan_partial_kernel<<<SCAN_NB, SCAN_BS>>>();
    scan_blocks_kernel<<<1, SCAN_BS>>>();
    scan_add_kernel<<<SCAN_NB, SCAN_BS>>>();
    build_kernel<<<(N_EDGES + 255) / 256, 256>>>(ev, es, ed);

    spmm_kernel<<<(N_NODES * 32 + 255) / 256, 256>>>(bias, out);
}